// round 1
// baseline (speedup 1.0000x reference)
#include <cuda_runtime.h>
#include <math.h>
#include <stdint.h>

#define B_    4
#define N_    8192
#define C_    512
#define H_    8
#define D_    64
#define M_    64           // window
#define NW    (N_ / M_)    // 128
#define ROWS  (B_ * N_)    // 32768
#define NEG_INF_F (-1000000000.0f)

// ---------------- scratch (static device globals: allocation-free) ------------
__device__ float g_Q[(size_t)ROWS * C_];      // 64 MB
__device__ float g_KV[(size_t)ROWS * C_];     // 64 MB
__device__ float g_attn_bnc[(size_t)ROWS * C_]; // 64 MB  attn in (B,N,C) layout
__device__ float g_ctx[16 * 64 * 64];         // raw context per (b, global-head)
__device__ float g_csum[16 * 64];             // per-column sum of exp(k)

// ---------------- SGEMM-NT: C[M,N] = A[M,K] * B[N,K]^T (+bias) ----------------
// BM=BN=128, BK=16, 256 threads, 8x8 per thread. M,N,K all multiples of tile.
__global__ __launch_bounds__(256) void sgemm_nt(
    const float* __restrict__ A, const float* __restrict__ Bm,
    float* __restrict__ C, int Ncols, int K, const float* __restrict__ bias)
{
    __shared__ float As[16][128];
    __shared__ float Bs[16][128];
    const int tid = threadIdx.x;
    const int tx = tid & 15, ty = tid >> 4;

    float acc[8][8];
#pragma unroll
    for (int i = 0; i < 8; i++)
#pragma unroll
        for (int j = 0; j < 8; j++) acc[i][j] = 0.f;

    const float* Ab = A + (size_t)blockIdx.y * 128 * K;
    const float* Bb = Bm + (size_t)blockIdx.x * 128 * K;

    for (int k0 = 0; k0 < K; k0 += 16) {
#pragma unroll
        for (int l = 0; l < 2; l++) {
            int i = tid + l * 256;                 // 0..511
            int row = i >> 2, kc = (i & 3) * 4;
            float4 va = *(const float4*)(Ab + (size_t)row * K + k0 + kc);
            As[kc + 0][row] = va.x; As[kc + 1][row] = va.y;
            As[kc + 2][row] = va.z; As[kc + 3][row] = va.w;
            float4 vb = *(const float4*)(Bb + (size_t)row * K + k0 + kc);
            Bs[kc + 0][row] = vb.x; Bs[kc + 1][row] = vb.y;
            Bs[kc + 2][row] = vb.z; Bs[kc + 3][row] = vb.w;
        }
        __syncthreads();
#pragma unroll
        for (int k = 0; k < 16; k++) {
            float4 a0 = *(const float4*)&As[k][ty * 8];
            float4 a1 = *(const float4*)&As[k][ty * 8 + 4];
            float4 b0 = *(const float4*)&Bs[k][tx * 8];
            float4 b1 = *(const float4*)&Bs[k][tx * 8 + 4];
            float av[8] = {a0.x, a0.y, a0.z, a0.w, a1.x, a1.y, a1.z, a1.w};
            float bv[8] = {b0.x, b0.y, b0.z, b0.w, b1.x, b1.y, b1.z, b1.w};
#pragma unroll
            for (int i = 0; i < 8; i++)
#pragma unroll
                for (int j = 0; j < 8; j++)
                    acc[i][j] = fmaf(av[i], bv[j], acc[i][j]);
        }
        __syncthreads();
    }

    const int row0 = blockIdx.y * 128 + ty * 8;
    const int col0 = blockIdx.x * 128 + tx * 8;
#pragma unroll
    for (int i = 0; i < 8; i++) {
        float* Cp = C + (size_t)(row0 + i) * Ncols + col0;
#pragma unroll
        for (int j = 0; j < 8; j++) {
            float v = acc[i][j];
            if (bias) v += bias[col0 + j];
            Cp[j] = v;
        }
    }
}

// ---------------- local window attention (heads 0..3) -------------------------
// one block per (window w, b*4+h). smem: q 64x68, k(=v) 192x68, scores 64x196.
#define QS 68
#define KS 68
#define SS 196
#define LA_SMEM ((64 * QS + 192 * KS + 64 * SS) * 4)

__global__ __launch_bounds__(256) void local_attn_kernel(float* __restrict__ attn_out)
{
    extern __shared__ float sm[];
    float* qs = sm;                    // 64 * QS
    float* ks = qs + 64 * QS;          // 192 * KS
    float* sc = ks + 192 * KS;         // 64 * SS

    const int w = blockIdx.x;
    const int bh = blockIdx.y;
    const int b = bh >> 2, h = bh & 3;
    const int t = threadIdx.x;
    const size_t rowbase = (size_t)b * N_ + (size_t)w * M_;
    const int col0 = h * D_;

    // load q (scaled by d^-0.5 = 0.125)
    for (int idx = t; idx < 64 * 16; idx += 256) {
        int r = idx >> 4, c4 = (idx & 15) * 4;
        float4 v = *(const float4*)(g_Q + (rowbase + r) * C_ + col0 + c4);
        float* dst = qs + r * QS + c4;
        dst[0] = v.x * 0.125f; dst[1] = v.y * 0.125f;
        dst[2] = v.z * 0.125f; dst[3] = v.w * 0.125f;
    }
    // load k (= v), 3 windows w-1,w,w+1; zero out-of-range rows
    const int nbase = (w - 1) * M_;
    for (int idx = t; idx < 192 * 16; idx += 256) {
        int r = idx >> 4, c4 = (idx & 15) * 4;
        int n = nbase + r;
        float4 v = make_float4(0.f, 0.f, 0.f, 0.f);
        if (n >= 0 && n < N_)
            v = *(const float4*)(g_KV + ((size_t)b * N_ + n) * C_ + col0 + c4);
        float* dst = ks + r * KS + c4;
        dst[0] = v.x; dst[1] = v.y; dst[2] = v.z; dst[3] = v.w;
    }
    __syncthreads();

    // scores: each thread computes 4 rows x 12 cols
    {
        const int ti = (t & 15) * 4;
        const int tj = (t >> 4) * 12;
        float a[4][12];
#pragma unroll
        for (int i = 0; i < 4; i++)
#pragma unroll
            for (int j = 0; j < 12; j++) a[i][j] = 0.f;

        for (int k4 = 0; k4 < 64; k4 += 4) {
            float4 qv[4];
#pragma unroll
            for (int i = 0; i < 4; i++)
                qv[i] = *(const float4*)&qs[(ti + i) * QS + k4];
#pragma unroll
            for (int j = 0; j < 12; j++) {
                float4 kv = *(const float4*)&ks[(tj + j) * KS + k4];
#pragma unroll
                for (int i = 0; i < 4; i++) {
                    a[i][j] = fmaf(qv[i].x, kv.x, a[i][j]);
                    a[i][j] = fmaf(qv[i].y, kv.y, a[i][j]);
                    a[i][j] = fmaf(qv[i].z, kv.z, a[i][j]);
                    a[i][j] = fmaf(qv[i].w, kv.w, a[i][j]);
                }
            }
        }
        const bool leftInv = (w == 0), rightInv = (w == NW - 1);
#pragma unroll
        for (int i = 0; i < 4; i++)
#pragma unroll
            for (int j = 0; j < 12; j++) {
                int jj = tj + j;
                float s = a[i][j];
                if ((jj < 64 && leftInv) || (jj >= 128 && rightInv)) s = NEG_INF_F;
                sc[(ti + i) * SS + jj] = s;
            }
    }
    __syncthreads();

    // softmax per row: 8 warps x 8 rows each
    {
        const int warp = t >> 5, lane = t & 31;
        for (int r = warp; r < 64; r += 8) {
            float m = -1e30f;
            for (int j = lane; j < 192; j += 32) m = fmaxf(m, sc[r * SS + j]);
#pragma unroll
            for (int o = 16; o; o >>= 1) m = fmaxf(m, __shfl_xor_sync(0xffffffffu, m, o));
            float s = 0.f;
            for (int j = lane; j < 192; j += 32) {
                float e = __expf(sc[r * SS + j] - m);
                sc[r * SS + j] = e;
                s += e;
            }
#pragma unroll
            for (int o = 16; o; o >>= 1) s += __shfl_xor_sync(0xffffffffu, s, o);
            float inv = 1.f / s;
            for (int j = lane; j < 192; j += 32) sc[r * SS + j] *= inv;
        }
    }
    __syncthreads();

    // out = probs @ v (v == k tile): each thread 4 rows x 4 cols
    {
        const int ti = (t & 15) * 4;
        const int te = (t >> 4) * 4;
        float a[4][4];
#pragma unroll
        for (int i = 0; i < 4; i++)
#pragma unroll
            for (int e = 0; e < 4; e++) a[i][e] = 0.f;

        for (int j = 0; j < 192; j++) {
            float4 vv = *(const float4*)&ks[j * KS + te];
#pragma unroll
            for (int i = 0; i < 4; i++) {
                float p = sc[(ti + i) * SS + j];
                a[i][0] = fmaf(p, vv.x, a[i][0]);
                a[i][1] = fmaf(p, vv.y, a[i][1]);
                a[i][2] = fmaf(p, vv.z, a[i][2]);
                a[i][3] = fmaf(p, vv.w, a[i][3]);
            }
        }
#pragma unroll
        for (int i = 0; i < 4; i++) {
            int n = w * M_ + ti + i;
            size_t o1 = ((size_t)(b * H_ + h) * N_ + n) * D_ + te;
            size_t o2 = ((size_t)b * N_ + n) * C_ + h * D_ + te;
#pragma unroll
            for (int e = 0; e < 4; e++) {
                attn_out[o1 + e] = a[i][e];
                g_attn_bnc[o2 + e] = a[i][e];
            }
        }
    }
}

// ---------------- linear attention (heads 4..7) -------------------------------
__global__ void zero_ctx_kernel()
{
    const int total = 16 * 4096 + 16 * 64;
    for (int i = blockIdx.x * blockDim.x + threadIdx.x; i < total;
         i += gridDim.x * blockDim.x) {
        if (i < 16 * 4096) g_ctx[i] = 0.f;
        else g_csum[i - 16 * 4096] = 0.f;
    }
}

// raw context: ctx[d][e] += exp(k[n,d]) * v[n,e]; csum[d] += exp(k[n,d])
// grid: (32 n-chunks of 256, 16 bh). k-values ~ N(0,1) so exp w/o max-sub is safe.
#define CT_SMEM (256 * 64 * 4)
__global__ __launch_bounds__(256) void ctx_kernel()
{
    extern __shared__ float tile[];     // [256][64], k == v
    const int bh = blockIdx.y;
    const int b = bh >> 2, h = 4 + (bh & 3);
    const int n0 = blockIdx.x * 256;
    const int t = threadIdx.x;

    const float* src = g_KV + ((size_t)b * N_ + n0) * C_ + h * D_;
    for (int idx = t; idx < 256 * 16; idx += 256) {
        int r = idx >> 4, c4 = (idx & 15) * 4;
        float4 v = *(const float4*)(src + (size_t)r * C_ + c4);
        float* dst = tile + r * 64 + c4;
        dst[0] = v.x; dst[1] = v.y; dst[2] = v.z; dst[3] = v.w;
    }
    __syncthreads();

    const int d = t >> 2, q = t & 3;
    float4 acc[4];
#pragma unroll
    for (int i = 0; i < 4; i++) acc[i] = make_float4(0.f, 0.f, 0.f, 0.f);
    float ssum = 0.f;

    for (int n = 0; n < 256; n++) {
        float ek = __expf(tile[n * 64 + d]);
        ssum += ek;
        const float4* vr = (const float4*)(tile + n * 64 + q * 16);
#pragma unroll
        for (int e4 = 0; e4 < 4; e4++) {
            float4 v = vr[e4];
            acc[e4].x = fmaf(ek, v.x, acc[e4].x);
            acc[e4].y = fmaf(ek, v.y, acc[e4].y);
            acc[e4].z = fmaf(ek, v.z, acc[e4].z);
            acc[e4].w = fmaf(ek, v.w, acc[e4].w);
        }
    }
    float* dst = g_ctx + bh * 4096 + d * 64 + q * 16;
#pragma unroll
    for (int e4 = 0; e4 < 4; e4++) {
        atomicAdd(dst + e4 * 4 + 0, acc[e4].x);
        atomicAdd(dst + e4 * 4 + 1, acc[e4].y);
        atomicAdd(dst + e4 * 4 + 2, acc[e4].z);
        atomicAdd(dst + e4 * 4 + 3, acc[e4].w);
    }
    if (q == 0) atomicAdd(&g_csum[bh * 64 + d], ssum);
}

// out[n,e] = sum_d softmax_d(q[n,:])[d] * d^-0.5 * ctx_raw[d,e] / csum[d]
// grid: (128 row-blocks of 64, 16 bh); one warp per row.
__global__ __launch_bounds__(256) void lin_out_kernel(float* __restrict__ attn_out)
{
    __shared__ float ctx_s[4096];
    __shared__ float cinv_s[64];
    const int bh = blockIdx.y;
    const int b = bh >> 2, h = 4 + (bh & 3);
    const int t = threadIdx.x;

    if (t < 64) cinv_s[t] = 1.f / g_csum[bh * 64 + t];
    for (int i = t; i < 4096; i += 256) ctx_s[i] = g_ctx[bh * 4096 + i];
    __syncthreads();

    const int warp = t >> 5, lane = t & 31;
    for (int r = warp; r < 64; r += 8) {
        const int n = blockIdx.x * 64 + r;
        const float* qrow = g_Q + ((size_t)b * N_ + n) * C_ + h * D_;
        float q0 = qrow[lane], q1 = qrow[lane + 32];
        float m = fmaxf(q0, q1);
#pragma unroll
        for (int o = 16; o; o >>= 1) m = fmaxf(m, __shfl_xor_sync(0xffffffffu, m, o));
        float e0 = __expf(q0 - m), e1 = __expf(q1 - m);
        float s = e0 + e1;
#pragma unroll
        for (int o = 16; o; o >>= 1) s += __shfl_xor_sync(0xffffffffu, s, o);
        float inv = 0.125f / s;           // includes d^-0.5
        e0 *= inv * cinv_s[lane];         // fold per-d 1/csum into softq
        e1 *= inv * cinv_s[lane + 32];

        float a0 = 0.f, a1 = 0.f;
#pragma unroll
        for (int dd = 0; dd < 64; dd++) {
            float sq = __shfl_sync(0xffffffffu, (dd < 32) ? e0 : e1, dd & 31);
            a0 = fmaf(sq, ctx_s[dd * 64 + lane], a0);
            a1 = fmaf(sq, ctx_s[dd * 64 + lane + 32], a1);
        }
        size_t o1 = ((size_t)(b * H_ + h) * N_ + n) * D_;
        attn_out[o1 + lane] = a0;
        attn_out[o1 + lane + 32] = a1;
        size_t o2 = ((size_t)b * N_ + n) * C_ + h * D_;
        g_attn_bnc[o2 + lane] = a0;
        g_attn_bnc[o2 + lane + 32] = a1;
    }
}

// ---------------------------------- launch ------------------------------------
extern "C" void kernel_launch(void* const* d_in, const int* in_sizes, int n_in,
                              void* d_out, int out_size)
{
    (void)in_sizes; (void)n_in; (void)out_size;
    const float* x     = (const float*)d_in[0];
    const float* Wq    = (const float*)d_in[1];
    const float* Wkv   = (const float*)d_in[2];
    const float* Wproj = (const float*)d_in[3];
    const float* bproj = (const float*)d_in[4];

    float* y    = (float*)d_out;                       // (B,N,C)
    float* attn = y + (size_t)ROWS * C_;               // (B,H,N,D)

    float *pQ, *pKV, *pAttn;
    cudaGetSymbolAddress((void**)&pQ, g_Q);
    cudaGetSymbolAddress((void**)&pKV, g_KV);
    cudaGetSymbolAddress((void**)&pAttn, g_attn_bnc);

    cudaFuncSetAttribute(local_attn_kernel,
                         cudaFuncAttributeMaxDynamicSharedMemorySize, LA_SMEM);
    cudaFuncSetAttribute(ctx_kernel,
                         cudaFuncAttributeMaxDynamicSharedMemorySize, CT_SMEM);

    dim3 gproj(C_ / 128, ROWS / 128);  // (4, 256)
    sgemm_nt<<<gproj, 256>>>(x, Wq, pQ, C_, C_, nullptr);
    sgemm_nt<<<gproj, 256>>>(x, Wkv, pKV, C_, C_, nullptr);

    local_attn_kernel<<<dim3(NW, 16), 256, LA_SMEM>>>(attn);

    zero_ctx_kernel<<<64, 256>>>();
    ctx_kernel<<<dim3(32, 16), 256, CT_SMEM>>>();
    lin_out_kernel<<<dim3(128, 16), 256>>>(attn);

    sgemm_nt<<<gproj, 256>>>(pAttn, Wproj, y, C_, C_, bproj);
}

// round 3
// speedup vs baseline: 1.4772x; 1.4772x over previous
#include <cuda_runtime.h>
#include <cuda_bf16.h>
#include <math.h>
#include <stdint.h>

#define B_    4
#define N_    8192
#define C_    512
#define K3    1536
#define H_    8
#define D_    64
#define M_    64           // window
#define NW    (N_ / M_)    // 128
#define ROWS  (B_ * N_)    // 32768
#define NEG_INF_F (-1000000000.0f)

// ---------------- scratch (static device globals: allocation-free) ------------
__device__ __align__(16) __nv_bfloat16 g_x3[(size_t)ROWS * K3];     // 96 MB [hi|lo|hi]
__device__ __align__(16) __nv_bfloat16 g_attn3[(size_t)ROWS * K3];  // 96 MB [hi|lo|hi]
__device__ __align__(16) __nv_bfloat16 g_Wq3[C_ * K3];              // [hi|hi|lo]
__device__ __align__(16) __nv_bfloat16 g_Wkv3[C_ * K3];
__device__ __align__(16) __nv_bfloat16 g_Wp3[C_ * K3];
__device__ float g_Q[(size_t)ROWS * C_];
__device__ float g_KV[(size_t)ROWS * C_];
__device__ float g_ctx[16 * 64 * 64];
__device__ float g_csum[16 * 64];

// ---------------- helpers -----------------------------------------------------
__device__ __forceinline__ uint32_t smem_u32(const void* p) {
    uint32_t a;
    asm("{ .reg .u64 t; cvta.to.shared.u64 t, %1; cvt.u32.u64 %0, t; }"
        : "=r"(a) : "l"(p));
    return a;
}
#define CP_ASYNC16(dst, src) \
    asm volatile("cp.async.cg.shared.global [%0], [%1], 16;" \
                 :: "r"(dst), "l"(src))
#define CP_COMMIT() asm volatile("cp.async.commit_group;" ::: "memory")
#define CP_WAIT1()  asm volatile("cp.async.wait_group 1;" ::: "memory")
#define CP_WAIT0()  asm volatile("cp.async.wait_group 0;" ::: "memory")

__device__ __forceinline__ void ldsm_x4(uint32_t& r0, uint32_t& r1,
                                        uint32_t& r2, uint32_t& r3, uint32_t addr) {
    asm volatile("ldmatrix.sync.aligned.m8n8.x4.shared.b16 {%0,%1,%2,%3}, [%4];"
                 : "=r"(r0), "=r"(r1), "=r"(r2), "=r"(r3) : "r"(addr));
}
__device__ __forceinline__ void mma_bf16(float* c, uint32_t a0, uint32_t a1,
                                         uint32_t a2, uint32_t a3,
                                         uint32_t b0, uint32_t b1) {
    asm volatile(
        "mma.sync.aligned.m16n8k16.row.col.f32.bf16.bf16.f32 "
        "{%0,%1,%2,%3}, {%4,%5,%6,%7}, {%8,%9}, {%0,%1,%2,%3};"
        : "+f"(c[0]), "+f"(c[1]), "+f"(c[2]), "+f"(c[3])
        : "r"(a0), "r"(a1), "r"(a2), "r"(a3), "r"(b0), "r"(b1));
}

// ---------------- hi/lo split conversion --------------------------------------
// mode 0 (A side): [hi | lo | hi]   mode 1 (B side): [hi | hi | lo]
__global__ __launch_bounds__(256) void split_kernel(
    const float* __restrict__ src, __nv_bfloat16* __restrict__ dst,
    int nrows, int mode)
{
    int total = nrows * (C_ / 4);
    for (int i = blockIdx.x * blockDim.x + threadIdx.x; i < total;
         i += gridDim.x * blockDim.x) {
        int r = i >> 7;             // C_/4 = 128
        int c = (i & 127) * 4;
        float4 v = *(const float4*)(src + (size_t)r * C_ + c);
        __nv_bfloat16 h0 = __float2bfloat16(v.x), h1 = __float2bfloat16(v.y);
        __nv_bfloat16 h2 = __float2bfloat16(v.z), h3 = __float2bfloat16(v.w);
        __nv_bfloat162 lo01 = __floats2bfloat162_rn(v.x - __bfloat162float(h0),
                                                    v.y - __bfloat162float(h1));
        __nv_bfloat162 lo23 = __floats2bfloat162_rn(v.z - __bfloat162float(h2),
                                                    v.w - __bfloat162float(h3));
        __nv_bfloat162 hi01; hi01.x = h0; hi01.y = h1;
        __nv_bfloat162 hi23; hi23.x = h2; hi23.y = h3;
        __nv_bfloat16* base = dst + (size_t)r * K3 + c;
        *(__nv_bfloat162*)(base + 0) = hi01;
        *(__nv_bfloat162*)(base + 2) = hi23;
        if (mode == 0) {
            *(__nv_bfloat162*)(base + 512) = lo01;
            *(__nv_bfloat162*)(base + 514) = lo23;
            *(__nv_bfloat162*)(base + 1024) = hi01;
            *(__nv_bfloat162*)(base + 1026) = hi23;
        } else {
            *(__nv_bfloat162*)(base + 512) = hi01;
            *(__nv_bfloat162*)(base + 514) = hi23;
            *(__nv_bfloat162*)(base + 1024) = lo01;
            *(__nv_bfloat162*)(base + 1026) = lo23;
        }
    }
}

// ---------------- bf16 mma.sync GEMM: C[m,n] = sum_k A3[m,k] B3[n,k] ----------
// 128x128 tile, BK=32, 256 threads, 8 warps as 4(m) x 2(n); warp tile 32x64.
// Double-buffered cp.async. Accumulate fp32.
__global__ __launch_bounds__(256, 2) void gemm_mma(
    const __nv_bfloat16* __restrict__ A3, const __nv_bfloat16* __restrict__ B3,
    float* __restrict__ Cout, const float* __restrict__ bias)
{
    __shared__ __nv_bfloat16 As[2][128][40];
    __shared__ __nv_bfloat16 Bs[2][128][40];

    const int tid = threadIdx.x;
    const int warp = tid >> 5, lane = tid & 31;
    const int wm = warp & 3, wn = warp >> 2;
    const int m0 = blockIdx.y * 128;
    const int n0 = blockIdx.x * 128;

    float acc[2][8][4];
#pragma unroll
    for (int i = 0; i < 2; i++)
#pragma unroll
        for (int j = 0; j < 8; j++)
#pragma unroll
            for (int e = 0; e < 4; e++) acc[i][j][e] = 0.f;

    const __nv_bfloat16* Ab = A3 + (size_t)m0 * K3;
    const __nv_bfloat16* Bb = B3 + (size_t)n0 * K3;

    // per-thread load coords: 512 16B-chunks per tile, 2 per thread
    const int lrow0 = tid >> 1;                  // 0..127
    const int lc0 = (tid & 1) * 2;               // chunk 0 or 2
    // chunks c and c+1 -> 2 x 16B contiguous = one row half

    // ldmatrix source addresses (within stage 0; stage stride added later)
    const int a_row = wm * 32 + (lane & 15);
    const int a_col = (lane >> 4) << 3;
    const int b_row = wn * 64 + ((lane >> 4) << 3) + (lane & 7);
    const int b_col = ((lane >> 3) & 1) << 3;

#define LOAD_TILES(s, j) do { \
    const int kofs = (j) * 32; \
    const __nv_bfloat16* asrc = Ab + (size_t)lrow0 * K3 + kofs + lc0 * 8; \
    uint32_t adst = smem_u32(&As[s][lrow0][lc0 * 8]); \
    CP_ASYNC16(adst, asrc); \
    CP_ASYNC16(adst + 16, asrc + 8); \
    const __nv_bfloat16* bsrc = Bb + (size_t)lrow0 * K3 + kofs + lc0 * 8; \
    uint32_t bdst = smem_u32(&Bs[s][lrow0][lc0 * 8]); \
    CP_ASYNC16(bdst, bsrc); \
    CP_ASYNC16(bdst + 16, bsrc + 8); \
} while (0)

    LOAD_TILES(0, 0);
    CP_COMMIT();

    for (int j = 0; j < 48; ++j) {
        const int s = j & 1;
        if (j < 47) {
            LOAD_TILES((j + 1) & 1, j + 1);
            CP_COMMIT();
            CP_WAIT1();
        } else {
            CP_WAIT0();
        }
        __syncthreads();

#pragma unroll
        for (int kk = 0; kk < 2; kk++) {
            const int k16 = kk * 16;
            uint32_t a[2][4];
#pragma unroll
            for (int i = 0; i < 2; i++)
                ldsm_x4(a[i][0], a[i][1], a[i][2], a[i][3],
                        smem_u32(&As[s][a_row + i * 16][k16 + a_col]));
            uint32_t b[4][4];
#pragma unroll
            for (int jb = 0; jb < 4; jb++)
                ldsm_x4(b[jb][0], b[jb][1], b[jb][2], b[jb][3],
                        smem_u32(&Bs[s][b_row + jb * 16][k16 + b_col]));
#pragma unroll
            for (int i = 0; i < 2; i++)
#pragma unroll
                for (int jn = 0; jn < 8; jn++) {
                    const int jb = jn >> 1, hf = (jn & 1) * 2;
                    mma_bf16(acc[i][jn], a[i][0], a[i][1], a[i][2], a[i][3],
                             b[jb][hf], b[jb][hf + 1]);
                }
        }
        __syncthreads();
    }

    // epilogue
#pragma unroll
    for (int i = 0; i < 2; i++) {
        const int r0 = m0 + wm * 32 + i * 16 + (lane >> 2);
#pragma unroll
        for (int jn = 0; jn < 8; jn++) {
            const int c0 = n0 + wn * 64 + jn * 8 + (lane & 3) * 2;
            float b0 = bias ? bias[c0] : 0.f;
            float b1 = bias ? bias[c0 + 1] : 0.f;
            float2 v0 = make_float2(acc[i][jn][0] + b0, acc[i][jn][1] + b1);
            float2 v1 = make_float2(acc[i][jn][2] + b0, acc[i][jn][3] + b1);
            *(float2*)(Cout + (size_t)r0 * C_ + c0) = v0;
            *(float2*)(Cout + (size_t)(r0 + 8) * C_ + c0) = v1;
        }
    }
}

// ---------------- local window attention (heads 0..3) -------------------------
#define QS 68
#define KS 68
#define SS 196
#define LA_SMEM ((64 * QS + 192 * KS + 64 * SS) * 4)

__global__ __launch_bounds__(256) void local_attn_kernel(float* __restrict__ attn_out)
{
    extern __shared__ float sm[];
    float* qs = sm;
    float* ks = qs + 64 * QS;
    float* sc = ks + 192 * KS;

    const int w = blockIdx.x;
    const int bh = blockIdx.y;
    const int b = bh >> 2, hh = bh & 3;
    const int t = threadIdx.x;
    const size_t rowbase = (size_t)b * N_ + (size_t)w * M_;
    const int col0 = hh * D_;

    for (int idx = t; idx < 64 * 16; idx += 256) {
        int r = idx >> 4, c4 = (idx & 15) * 4;
        float4 v = *(const float4*)(g_Q + (rowbase + r) * C_ + col0 + c4);
        float* dst = qs + r * QS + c4;
        dst[0] = v.x * 0.125f; dst[1] = v.y * 0.125f;
        dst[2] = v.z * 0.125f; dst[3] = v.w * 0.125f;
    }
    const int nbase = (w - 1) * M_;
    for (int idx = t; idx < 192 * 16; idx += 256) {
        int r = idx >> 4, c4 = (idx & 15) * 4;
        int n = nbase + r;
        float4 v = make_float4(0.f, 0.f, 0.f, 0.f);
        if (n >= 0 && n < N_)
            v = *(const float4*)(g_KV + ((size_t)b * N_ + n) * C_ + col0 + c4);
        float* dst = ks + r * KS + c4;
        dst[0] = v.x; dst[1] = v.y; dst[2] = v.z; dst[3] = v.w;
    }
    __syncthreads();

    {
        const int ti = (t & 15) * 4;
        const int tj = (t >> 4) * 12;
        float a[4][12];
#pragma unroll
        for (int i = 0; i < 4; i++)
#pragma unroll
            for (int j = 0; j < 12; j++) a[i][j] = 0.f;

        for (int k4 = 0; k4 < 64; k4 += 4) {
            float4 qv[4];
#pragma unroll
            for (int i = 0; i < 4; i++)
                qv[i] = *(const float4*)&qs[(ti + i) * QS + k4];
#pragma unroll
            for (int j = 0; j < 12; j++) {
                float4 kv = *(const float4*)&ks[(tj + j) * KS + k4];
#pragma unroll
                for (int i = 0; i < 4; i++) {
                    a[i][j] = fmaf(qv[i].x, kv.x, a[i][j]);
                    a[i][j] = fmaf(qv[i].y, kv.y, a[i][j]);
                    a[i][j] = fmaf(qv[i].z, kv.z, a[i][j]);
                    a[i][j] = fmaf(qv[i].w, kv.w, a[i][j]);
                }
            }
        }
        const bool leftInv = (w == 0), rightInv = (w == NW - 1);
#pragma unroll
        for (int i = 0; i < 4; i++)
#pragma unroll
            for (int j = 0; j < 12; j++) {
                int jj = tj + j;
                float s = a[i][j];
                if ((jj < 64 && leftInv) || (jj >= 128 && rightInv)) s = NEG_INF_F;
                sc[(ti + i) * SS + jj] = s;
            }
    }
    __syncthreads();

    {
        const int warp = t >> 5, lane = t & 31;
        for (int r = warp; r < 64; r += 8) {
            float m = -1e30f;
            for (int j = lane; j < 192; j += 32) m = fmaxf(m, sc[r * SS + j]);
#pragma unroll
            for (int o = 16; o; o >>= 1) m = fmaxf(m, __shfl_xor_sync(0xffffffffu, m, o));
            float s = 0.f;
            for (int j = lane; j < 192; j += 32) {
                float e = __expf(sc[r * SS + j] - m);
                sc[r * SS + j] = e;
                s += e;
            }
#pragma unroll
            for (int o = 16; o; o >>= 1) s += __shfl_xor_sync(0xffffffffu, s, o);
            float inv = 1.f / s;
            for (int j = lane; j < 192; j += 32) sc[r * SS + j] *= inv;
        }
    }
    __syncthreads();

    {
        const int ti = (t & 15) * 4;
        const int te = (t >> 4) * 4;
        float a[4][4];
#pragma unroll
        for (int i = 0; i < 4; i++)
#pragma unroll
            for (int e = 0; e < 4; e++) a[i][e] = 0.f;

        for (int j = 0; j < 192; j++) {
            float4 vv = *(const float4*)&ks[j * KS + te];
#pragma unroll
            for (int i = 0; i < 4; i++) {
                float pcoef = sc[(ti + i) * SS + j];
                a[i][0] = fmaf(pcoef, vv.x, a[i][0]);
                a[i][1] = fmaf(pcoef, vv.y, a[i][1]);
                a[i][2] = fmaf(pcoef, vv.z, a[i][2]);
                a[i][3] = fmaf(pcoef, vv.w, a[i][3]);
            }
        }
#pragma unroll
        for (int i = 0; i < 4; i++) {
            int n = w * M_ + ti + i;
            size_t o1 = ((size_t)(b * H_ + hh) * N_ + n) * D_ + te;
#pragma unroll
            for (int e = 0; e < 4; e++) attn_out[o1 + e] = a[i][e];

            // fused hi/lo bf16 write for projection GEMM ([hi|lo|hi])
            __nv_bfloat16 h0 = __float2bfloat16(a[i][0]);
            __nv_bfloat16 h1 = __float2bfloat16(a[i][1]);
            __nv_bfloat16 h2 = __float2bfloat16(a[i][2]);
            __nv_bfloat16 h3 = __float2bfloat16(a[i][3]);
            __nv_bfloat162 lo01 = __floats2bfloat162_rn(
                a[i][0] - __bfloat162float(h0), a[i][1] - __bfloat162float(h1));
            __nv_bfloat162 lo23 = __floats2bfloat162_rn(
                a[i][2] - __bfloat162float(h2), a[i][3] - __bfloat162float(h3));
            __nv_bfloat162 hi01; hi01.x = h0; hi01.y = h1;
            __nv_bfloat162 hi23; hi23.x = h2; hi23.y = h3;
            __nv_bfloat16* b3 = g_attn3 + ((size_t)b * N_ + n) * K3 + hh * D_ + te;
            *(__nv_bfloat162*)(b3 + 0) = hi01;
            *(__nv_bfloat162*)(b3 + 2) = hi23;
            *(__nv_bfloat162*)(b3 + 512) = lo01;
            *(__nv_bfloat162*)(b3 + 514) = lo23;
            *(__nv_bfloat162*)(b3 + 1024) = hi01;
            *(__nv_bfloat162*)(b3 + 1026) = hi23;
        }
    }
}

// ---------------- linear attention (heads 4..7) -------------------------------
__global__ void zero_ctx_kernel()
{
    const int total = 16 * 4096 + 16 * 64;
    for (int i = blockIdx.x * blockDim.x + threadIdx.x; i < total;
         i += gridDim.x * blockDim.x) {
        if (i < 16 * 4096) g_ctx[i] = 0.f;
        else g_csum[i - 16 * 4096] = 0.f;
    }
}

#define CT_SMEM (256 * 64 * 4)
__global__ __launch_bounds__(256) void ctx_kernel()
{
    extern __shared__ float tile[];
    const int bh = blockIdx.y;
    const int b = bh >> 2, hh = 4 + (bh & 3);
    const int n0 = blockIdx.x * 256;
    const int t = threadIdx.x;

    const float* src = g_KV + ((size_t)b * N_ + n0) * C_ + hh * D_;
    for (int idx = t; idx < 256 * 16; idx += 256) {
        int r = idx >> 4, c4 = (idx & 15) * 4;
        float4 v = *(const float4*)(src + (size_t)r * C_ + c4);
        float* dst = tile + r * 64 + c4;
        dst[0] = v.x; dst[1] = v.y; dst[2] = v.z; dst[3] = v.w;
    }
    __syncthreads();

    const int d = t >> 2, q = t & 3;
    float4 acc[4];
#pragma unroll
    for (int i = 0; i < 4; i++) acc[i] = make_float4(0.f, 0.f, 0.f, 0.f);
    float ssum = 0.f;

    for (int n = 0; n < 256; n++) {
        float ek = __expf(tile[n * 64 + d]);
        ssum += ek;
        const float4* vr = (const float4*)(tile + n * 64 + q * 16);
#pragma unroll
        for (int e4 = 0; e4 < 4; e4++) {
            float4 v = vr[e4];
            acc[e4].x = fmaf(ek, v.x, acc[e4].x);
            acc[e4].y = fmaf(ek, v.y, acc[e4].y);
            acc[e4].z = fmaf(ek, v.z, acc[e4].z);
            acc[e4].w = fmaf(ek, v.w, acc[e4].w);
        }
    }
    float* dst = g_ctx + bh * 4096 + d * 64 + q * 16;
#pragma unroll
    for (int e4 = 0; e4 < 4; e4++) {
        atomicAdd(dst + e4 * 4 + 0, acc[e4].x);
        atomicAdd(dst + e4 * 4 + 1, acc[e4].y);
        atomicAdd(dst + e4 * 4 + 2, acc[e4].z);
        atomicAdd(dst + e4 * 4 + 3, acc[e4].w);
    }
    if (q == 0) atomicAdd(&g_csum[bh * 64 + d], ssum);
}

__global__ __launch_bounds__(256) void lin_out_kernel(float* __restrict__ attn_out)
{
    __shared__ float ctx_s[4096];
    __shared__ float cinv_s[64];
    const int bh = blockIdx.y;
    const int b = bh >> 2, hh = 4 + (bh & 3);
    const int t = threadIdx.x;

    if (t < 64) cinv_s[t] = 1.f / g_csum[bh * 64 + t];
    for (int i = t; i < 4096; i += 256) ctx_s[i] = g_ctx[bh * 4096 + i];
    __syncthreads();

    const int warp = t >> 5, lane = t & 31;
    for (int r = warp; r < 64; r += 8) {
        const int n = blockIdx.x * 64 + r;
        const float* qrow = g_Q + ((size_t)b * N_ + n) * C_ + hh * D_;
        float q0 = qrow[lane], q1 = qrow[lane + 32];
        float m = fmaxf(q0, q1);
#pragma unroll
        for (int o = 16; o; o >>= 1) m = fmaxf(m, __shfl_xor_sync(0xffffffffu, m, o));
        float e0 = __expf(q0 - m), e1 = __expf(q1 - m);
        float s = e0 + e1;
#pragma unroll
        for (int o = 16; o; o >>= 1) s += __shfl_xor_sync(0xffffffffu, s, o);
        float inv = 0.125f / s;
        e0 *= inv * cinv_s[lane];
        e1 *= inv * cinv_s[lane + 32];

        float a0 = 0.f, a1 = 0.f;
#pragma unroll
        for (int dd = 0; dd < 64; dd++) {
            float sq = __shfl_sync(0xffffffffu, (dd < 32) ? e0 : e1, dd & 31);
            a0 = fmaf(sq, ctx_s[dd * 64 + lane], a0);
            a1 = fmaf(sq, ctx_s[dd * 64 + lane + 32], a1);
        }
        size_t o1 = ((size_t)(b * H_ + hh) * N_ + n) * D_;
        attn_out[o1 + lane] = a0;
        attn_out[o1 + lane + 32] = a1;

        // fused hi/lo bf16 write ([hi|lo|hi])
        __nv_bfloat16 a0h = __float2bfloat16(a0);
        __nv_bfloat16 a1h = __float2bfloat16(a1);
        __nv_bfloat16 a0l = __float2bfloat16(a0 - __bfloat162float(a0h));
        __nv_bfloat16 a1l = __float2bfloat16(a1 - __bfloat162float(a1h));
        __nv_bfloat16* b3 = g_attn3 + ((size_t)b * N_ + n) * K3 + hh * D_;
        b3[lane] = a0h;           b3[lane + 32] = a1h;
        b3[512 + lane] = a0l;     b3[512 + lane + 32] = a1l;
        b3[1024 + lane] = a0h;    b3[1024 + lane + 32] = a1h;
    }
}

// ---------------------------------- launch ------------------------------------
extern "C" void kernel_launch(void* const* d_in, const int* in_sizes, int n_in,
                              void* d_out, int out_size)
{
    (void)in_sizes; (void)n_in; (void)out_size;
    const float* x     = (const float*)d_in[0];
    const float* Wq    = (const float*)d_in[1];
    const float* Wkv   = (const float*)d_in[2];
    const float* Wproj = (const float*)d_in[3];
    const float* bproj = (const float*)d_in[4];

    float* y    = (float*)d_out;
    float* attn = y + (size_t)ROWS * C_;

    float *pQ, *pKV;
    __nv_bfloat16 *px3, *pa3, *pWq3, *pWkv3, *pWp3;
    cudaGetSymbolAddress((void**)&pQ, g_Q);
    cudaGetSymbolAddress((void**)&pKV, g_KV);
    cudaGetSymbolAddress((void**)&px3, g_x3);
    cudaGetSymbolAddress((void**)&pa3, g_attn3);
    cudaGetSymbolAddress((void**)&pWq3, g_Wq3);
    cudaGetSymbolAddress((void**)&pWkv3, g_Wkv3);
    cudaGetSymbolAddress((void**)&pWp3, g_Wp3);

    cudaFuncSetAttribute(local_attn_kernel,
                         cudaFuncAttributeMaxDynamicSharedMemorySize, LA_SMEM);
    cudaFuncSetAttribute(ctx_kernel,
                         cudaFuncAttributeMaxDynamicSharedMemorySize, CT_SMEM);

    // conversions
    split_kernel<<<4096, 256>>>(x, px3, ROWS, 0);
    split_kernel<<<128, 256>>>(Wq, pWq3, C_, 1);
    split_kernel<<<128, 256>>>(Wkv, pWkv3, C_, 1);
    split_kernel<<<128, 256>>>(Wproj, pWp3, C_, 1);

    dim3 ggemm(C_ / 128, ROWS / 128);   // (4, 256)
    gemm_mma<<<ggemm, 256>>>(px3, pWq3, pQ, nullptr);
    gemm_mma<<<ggemm, 256>>>(px3, pWkv3, pKV, nullptr);

    local_attn_kernel<<<dim3(NW, 16), 256, LA_SMEM>>>(attn);

    zero_ctx_kernel<<<64, 256>>>();
    ctx_kernel<<<dim3(32, 16), 256, CT_SMEM>>>();
    lin_out_kernel<<<dim3(128, 16), 256>>>(attn);

    gemm_mma<<<ggemm, 256>>>(pa3, pWp3, y, bproj);
}